// round 16
// baseline (speedup 1.0000x reference)
#include <cuda_runtime.h>
#include <cuda_fp16.h>
#include <cstdint>

// ----------------------------------------------------------------------------
// GNNLayer: out = relu(x @ W^T + b); out[col[e],0] += x[e,0]
// Fused fp16 mma.sync GEMM: cp.async fp32 x -> A32 staging -> cooperative
// convert to fp16 -> ldmatrix. 256 threads, 64x32 warp tiles, 2 CTAs/SM
// (16 warps/SM = R7's proven latency-hiding point, now with fused convert).
// Prep kernel: W fp16 + scatter sums S; S applied in epilogue (read+zero).
// ----------------------------------------------------------------------------

#define IN_DIM  512
#define OUT_DIM 512
#define MAXROWS 100096
#define BM      128
#define BN      128
#define BK      64
#define NCHUNK  (IN_DIM / BK)   // 8
#define THREADS 256

// A32 staging: 272B rows (68w == 4 mod 32, LDS.128 conflict-free).
// A16/B: 144B rows (ldmatrix conflict-free).
#define A32_ROWB 272
#define A16_ROWB 144
#define B_ROWB   144
#define SM_A32   0
#define A32_SIZE (BM * A32_ROWB)                 // 34816
#define SM_A16   A32_SIZE                         // + st*A16_SIZE
#define A16_SIZE (BM * A16_ROWB)                 // 18432
#define SM_B     (A32_SIZE + 2 * A16_SIZE)       // 71680, + st*B_SIZE
#define B_SIZE   (BM * B_ROWB)                   // 18432
#define SM_TOTAL (SM_B + 2 * B_SIZE)             // 108544 (x2 CTA = 217088)

__device__ __half g_Wh[OUT_DIM * IN_DIM];
__device__ float  g_S[MAXROWS];                  // per-row scatter sums (col 0)

__device__ __forceinline__ uint32_t smem_u32(const void* p) {
    uint32_t a;
    asm("{ .reg .u64 t; cvta.to.shared.u64 t, %1; cvt.u32.u64 %0, t; }" : "=r"(a) : "l"(p));
    return a;
}
__device__ __forceinline__ void ldx4(uint32_t r[4], uint32_t addr) {
    asm volatile("ldmatrix.sync.aligned.m8n8.x4.shared.b16 {%0,%1,%2,%3}, [%4];"
                 : "=r"(r[0]), "=r"(r[1]), "=r"(r[2]), "=r"(r[3]) : "r"(addr));
}
__device__ __forceinline__ void ldx2(uint32_t r[2], uint32_t addr) {
    asm volatile("ldmatrix.sync.aligned.m8n8.x2.shared.b16 {%0,%1}, [%2];"
                 : "=r"(r[0]), "=r"(r[1]) : "r"(addr));
}
__device__ __forceinline__ void mma16816(float c[4], const uint32_t a[4], const uint32_t b[2]) {
    asm volatile("mma.sync.aligned.m16n8k16.row.col.f32.f16.f16.f32 "
                 "{%0,%1,%2,%3}, {%4,%5,%6,%7}, {%8,%9}, {%0,%1,%2,%3};"
                 : "+f"(c[0]), "+f"(c[1]), "+f"(c[2]), "+f"(c[3])
                 : "r"(a[0]), "r"(a[1]), "r"(a[2]), "r"(a[3]), "r"(b[0]), "r"(b[1]));
}
__device__ __forceinline__ void cp16(uint32_t dst, const void* src) {
    asm volatile("cp.async.cg.shared.global [%0], [%1], 16;"
                 :: "r"(dst), "l"(__cvta_generic_to_global(src)));
}
__device__ __forceinline__ float4 lds128f(uint32_t addr) {
    float4 v;
    asm volatile("ld.shared.v4.f32 {%0,%1,%2,%3}, [%4];"
                 : "=f"(v.x), "=f"(v.y), "=f"(v.z), "=f"(v.w) : "r"(addr));
    return v;
}
__device__ __forceinline__ void sts128(uint32_t addr, uint32_t a, uint32_t b,
                                       uint32_t c, uint32_t d) {
    asm volatile("st.shared.v4.b32 [%0], {%1,%2,%3,%4};"
                 :: "r"(addr), "r"(a), "r"(b), "r"(c), "r"(d) : "memory");
}
__device__ __forceinline__ uint32_t packh2(float a, float b) {
    __half2 h = __floats2half2_rn(a, b);
    return *reinterpret_cast<uint32_t*>(&h);
}

// ---------------- prep: W fp32->fp16 AND scatter-sum S ------------------------
#define WN4 (OUT_DIM * IN_DIM / 4)               // 65536
__global__ __launch_bounds__(256)
void prep_kernel(const float* __restrict__ W,
                 const float* __restrict__ x,
                 const int* __restrict__ edge_index, int E) {
    int i = blockIdx.x * blockDim.x + threadIdx.x;
    if (i < WN4) {
        float4 v = reinterpret_cast<const float4*>(W)[i];
        uint2 o;
        o.x = packh2(v.x, v.y);
        o.y = packh2(v.z, v.w);
        reinterpret_cast<uint2*>(g_Wh)[i] = o;
    }
    if (i < E) {
        int c = edge_index[E + i];                // row 1 of [2,E] int32
        atomicAdd(&g_S[c], x[(size_t)i * IN_DIM]);
    }
}

// ---------------- main GEMM kernel --------------------------------------------
__global__ __launch_bounds__(THREADS, 2)
void gemm_mma_kernel(const float* __restrict__ A,      // fp32 x
                     const float* __restrict__ bias,
                     float* __restrict__ C, int M) {
    extern __shared__ char smem[];
    const uint32_t sb = smem_u32(smem);
    const int tid    = threadIdx.x;
    const int lane   = tid & 31;
    const int wid    = tid >> 5;          // 0..7
    const int warp_m = wid >> 2;          // 0..1 (64 rows)
    const int warp_n = wid & 3;           // 0..3 (32 cols)
    const int row0   = blockIdx.y * BM;
    const int n0     = blockIdx.x * BN;

    // ldmatrix lane addressing (R7-proven)
    const uint32_t arow  = (uint32_t)(warp_m * 64 + (lane & 15));
    const uint32_t acolq = (uint32_t)((lane >> 4) << 3) * 2;       // 0 or 16B
    const uint32_t brow8 = (uint32_t)(lane & 7);
    const uint32_t bcolq = (uint32_t)(((lane >> 3) & 1) * 8) * 2;  // 0 or 16B

    float acc[4][4][4];
    #pragma unroll
    for (int mi = 0; mi < 4; mi++)
        #pragma unroll
        for (int ni = 0; ni < 4; ni++)
            #pragma unroll
            for (int j = 0; j < 4; j++) acc[mi][ni][j] = 0.f;

    auto issueA32 = [&](int kt) {
        const int k0 = kt * BK;
        #pragma unroll
        for (int i = 0; i < 8; i++) {
            int idx = i * THREADS + tid;
            int r = idx >> 4, u = idx & 15;
            int gr = row0 + r;
            if (gr < M)
                cp16(sb + SM_A32 + r * A32_ROWB + u * 16,
                     A + (size_t)gr * IN_DIM + k0 + u * 4);
        }
    };
    auto issueB = [&](int kt, int st) {
        const int k0 = kt * BK;
        #pragma unroll
        for (int i = 0; i < 4; i++) {
            int idx = i * THREADS + tid;
            int r = idx >> 3, u = idx & 7;
            cp16(sb + SM_B + st * B_SIZE + r * B_ROWB + u * 16,
                 g_Wh + (size_t)(n0 + r) * IN_DIM + k0 + u * 8);
        }
    };

    // cooperative convert over 256 threads: thread t handles row (t&127),
    // half (t>>7): 32 floats = 4 LDS.128 -> 2 STS.128 (64B fp16)
    auto convertA = [&](int st) {
        const int r    = tid & 127;
        const int half = tid >> 7;            // 0 or 1
        const uint32_t src = sb + SM_A32 + r * A32_ROWB + half * 128;
        const uint32_t dst = sb + SM_A16 + st * A16_SIZE + r * A16_ROWB + half * 64;
        #pragma unroll
        for (int i = 0; i < 2; i++) {
            float4 v0 = lds128f(src + (2 * i) * 16);
            float4 v1 = lds128f(src + (2 * i + 1) * 16);
            sts128(dst + i * 16,
                   packh2(v0.x, v0.y), packh2(v0.z, v0.w),
                   packh2(v1.x, v1.y), packh2(v1.z, v1.w));
        }
        #pragma unroll
        for (int i = 2; i < 4; i++) {
            float4 v0 = lds128f(src + (2 * i) * 16);
            float4 v1 = lds128f(src + (2 * i + 1) * 16);
            sts128(dst + i * 16,
                   packh2(v0.x, v0.y), packh2(v0.z, v0.w),
                   packh2(v1.x, v1.y), packh2(v1.z, v1.w));
        }
    };

    // ---- prologue -----------------------------------------------------------
    issueA32(0);
    issueB(0, 0);
    asm volatile("cp.async.commit_group;" ::: "memory");

    // ---- main loop ----------------------------------------------------------
    for (int kt = 0; kt < NCHUNK; kt++) {
        const int st = kt & 1;
        asm volatile("cp.async.wait_group 0;" ::: "memory");   // chunk kt landed
        __syncthreads();

        convertA(st);                                          // A32 -> A16(st)
        __syncthreads();                                       // A16 ready; A32 free

        if (kt + 1 < NCHUNK) { issueA32(kt + 1); issueB(kt + 1, st ^ 1); }
        asm volatile("cp.async.commit_group;" ::: "memory");   // (possibly empty)

        const uint32_t sbA = sb + SM_A16 + st * A16_SIZE;
        const uint32_t sbB = sb + SM_B   + st * B_SIZE;
        #pragma unroll
        for (int s = 0; s < 4; s++) {
            const uint32_t kb = (uint32_t)(s * 16) * 2;        // 32B per k16

            uint32_t af[4][4];
            #pragma unroll
            for (int mi = 0; mi < 4; mi++)
                ldx4(af[mi], sbA + (arow + mi * 16) * A16_ROWB + kb + acolq);

            uint32_t bf[4][2];
            #pragma unroll
            for (int ni = 0; ni < 4; ni++)
                ldx2(bf[ni], sbB + (warp_n * 32 + ni * 8 + brow8) * B_ROWB + kb + bcolq);

            #pragma unroll
            for (int mi = 0; mi < 4; mi++)
                #pragma unroll
                for (int ni = 0; ni < 4; ni++)
                    mma16816(acc[mi][ni], af[mi], bf[ni]);
        }
    }

    // ---- epilogue: bias + relu (+ scatter S on column 0) + float2 stores ----
    const bool col0_owner = (blockIdx.x == 0) && (warp_n == 0) && ((lane & 3) == 0);
    #pragma unroll
    for (int mi = 0; mi < 4; mi++) {
        int r = row0 + warp_m * 64 + mi * 16 + (lane >> 2);
        #pragma unroll
        for (int ni = 0; ni < 4; ni++) {
            int col = n0 + warp_n * 32 + ni * 8 + (lane & 3) * 2;
            float2 bv = *reinterpret_cast<const float2*>(bias + col);
            if (r < M) {
                float2 o;
                o.x = fmaxf(acc[mi][ni][0] + bv.x, 0.f);
                o.y = fmaxf(acc[mi][ni][1] + bv.y, 0.f);
                if (ni == 0 && col0_owner) {      // col == 0
                    o.x += g_S[r];
                    g_S[r] = 0.f;                 // restore for next replay
                }
                *reinterpret_cast<float2*>(C + (size_t)r * OUT_DIM + col) = o;
            }
            if (r + 8 < M) {
                float2 o;
                o.x = fmaxf(acc[mi][ni][2] + bv.x, 0.f);
                o.y = fmaxf(acc[mi][ni][3] + bv.y, 0.f);
                if (ni == 0 && col0_owner) {      // col == 0, row r+8
                    o.x += g_S[r + 8];
                    g_S[r + 8] = 0.f;
                }
                *reinterpret_cast<float2*>(C + (size_t)(r + 8) * OUT_DIM + col) = o;
            }
        }
    }
}

// ---------------- launch ------------------------------------------------------
extern "C" void kernel_launch(void* const* d_in, const int* in_sizes, int n_in,
                              void* d_out, int out_size) {
    const float* x   = (const float*)d_in[0];
    const int*   ei  = (const int*)d_in[1];
    const float* W   = (const float*)d_in[2];
    const float* b   = (const float*)d_in[3];
    float*       out = (float*)d_out;

    const int M = in_sizes[0] / IN_DIM;
    const int E = in_sizes[1] / 2;

    cudaFuncSetAttribute(gemm_mma_kernel, cudaFuncAttributeMaxDynamicSharedMemorySize, SM_TOTAL);

    const int prep_n = (E > WN4) ? E : WN4;
    prep_kernel<<<(prep_n + 255) / 256, 256>>>(W, x, ei, E);

    dim3 grid(OUT_DIM / BN, (M + BM - 1) / BM);   // 4 x 782
    gemm_mma_kernel<<<grid, THREADS, SM_TOTAL>>>(x, b, out, M);
}

// round 17
// speedup vs baseline: 1.2495x; 1.2495x over previous
#include <cuda_runtime.h>
#include <cuda_fp16.h>
#include <cstdint>

// ----------------------------------------------------------------------------
// GNNLayer: out = relu(x @ W^T + b); out[col[e],0] += x[e,0]
// fp16 mma.sync GEMM with FUSED x fp32->fp16 conversion:
//   A: cp.async fp32 -> smem(288B rows) -> LDS.64 + cvt to fragments
//   B: fp16 (prep) -> cp.async -> ldmatrix
// CTA 128x128, 4 warps (2x2) of 64x64, 2 stages, 2 CTAs/SM.
// (R12 champion configuration: measured 187.0us; R13-R16 excursions all
//  regressed, establishing this as the plateau for the mma.sync path.)
// ----------------------------------------------------------------------------

#define IN_DIM  512
#define OUT_DIM 512
#define BM      128
#define BN      128
#define BK      64
#define NCHUNK  (IN_DIM / BK)   // 8
#define THREADS 128

// A fp32 tile: 128 rows x 64 floats; row stride 288B (256 + 32 pad):
// 72 words == 8 mod 32 -> fragment LDS.64 pattern conflict-free.
#define A32_ROWB 288
// B fp16 tile: 128 rows x 64 halves; row stride 144B (ldmatrix conflict-free).
#define B_ROWB   144
#define SM_A     0
#define SM_B     (BM * A32_ROWB)             // 36864
#define STAGE    (SM_B + BM * B_ROWB)        // 55296
#define NSTAGE   2
#define SM_TOTAL (NSTAGE * STAGE)            // 110592 (x2 CTA = 221184 <= 228KB)

__device__ __half g_Wh[OUT_DIM * IN_DIM];

__device__ __forceinline__ uint32_t smem_u32(const void* p) {
    uint32_t a;
    asm("{ .reg .u64 t; cvta.to.shared.u64 t, %1; cvt.u32.u64 %0, t; }" : "=r"(a) : "l"(p));
    return a;
}
__device__ __forceinline__ void ldx2(uint32_t r[2], uint32_t addr) {
    asm volatile("ldmatrix.sync.aligned.m8n8.x2.shared.b16 {%0,%1}, [%2];"
                 : "=r"(r[0]), "=r"(r[1]) : "r"(addr));
}
__device__ __forceinline__ void mma16816(float c[4], const uint32_t a[4], const uint32_t b[2]) {
    asm volatile("mma.sync.aligned.m16n8k16.row.col.f32.f16.f16.f32 "
                 "{%0,%1,%2,%3}, {%4,%5,%6,%7}, {%8,%9}, {%0,%1,%2,%3};"
                 : "+f"(c[0]), "+f"(c[1]), "+f"(c[2]), "+f"(c[3])
                 : "r"(a[0]), "r"(a[1]), "r"(a[2]), "r"(a[3]), "r"(b[0]), "r"(b[1]));
}
__device__ __forceinline__ void cp16(uint32_t dst, const void* src) {
    asm volatile("cp.async.cg.shared.global [%0], [%1], 16;"
                 :: "r"(dst), "l"(__cvta_generic_to_global(src)));
}
// LDS.64 of two fp32 from shared, convert to packed fp16x2 (low = first)
__device__ __forceinline__ uint32_t lds2cvt(uint32_t addr) {
    float f0, f1;
    asm volatile("ld.shared.v2.f32 {%0, %1}, [%2];" : "=f"(f0), "=f"(f1) : "r"(addr));
    __half2 h = __floats2half2_rn(f0, f1);
    return *reinterpret_cast<uint32_t*>(&h);
}

// ---------------- prep: convert W to fp16 (1MB, ~4.8us) -----------------------
__global__ void conv_W_kernel(const float* __restrict__ W) {
    int i = blockIdx.x * blockDim.x + threadIdx.x;
    if (i < OUT_DIM * IN_DIM) g_Wh[i] = __float2half_rn(W[i]);
}

// ---------------- main GEMM kernel --------------------------------------------
__global__ __launch_bounds__(THREADS, 2)
void gemm_mma_kernel(const float* __restrict__ A,      // fp32 x
                     const float* __restrict__ bias,
                     float* __restrict__ C, int M) {
    extern __shared__ char smem[];
    const uint32_t sb = smem_u32(smem);
    const int tid    = threadIdx.x;
    const int lane   = tid & 31;
    const int wid    = tid >> 5;          // 0..3
    const int warp_m = wid >> 1;          // 0..1 (64 rows)
    const int warp_n = wid & 1;           // 0..1 (64 cols)
    const int row0   = blockIdx.y * BM;
    const int n0     = blockIdx.x * BN;

    // A fragment addressing (fp32 in smem): lane covers rows +lane/4, k-offsets 2*(lane%4)
    const uint32_t a_r  = (uint32_t)(warp_m * 64 + (lane >> 2));
    const uint32_t a_c  = (uint32_t)(2 * (lane & 3));              // float offset
    // B ldmatrix addressing (fp16)
    const uint32_t brow8 = (uint32_t)(lane & 7);
    const uint32_t bcolq = (uint32_t)(((lane >> 3) & 1) * 8) * 2;  // 0 or 16B

    float acc[4][8][4];
    #pragma unroll
    for (int mi = 0; mi < 4; mi++)
        #pragma unroll
        for (int ni = 0; ni < 8; ni++)
            #pragma unroll
            for (int j = 0; j < 4; j++) acc[mi][ni][j] = 0.f;

    auto issue = [&](int kt, int st) {
        const int k0 = kt * BK;
        const uint32_t sbase = sb + st * STAGE;
        // A: fp32, 128 rows x 16 units of 16B = 2048 cp16 (16/thread), guarded
        #pragma unroll
        for (int i = 0; i < 16; i++) {
            int idx = i * THREADS + tid;
            int r = idx >> 4, u = idx & 15;
            int gr = row0 + r;
            if (gr < M)
                cp16(sbase + SM_A + r * A32_ROWB + u * 16,
                     A + (size_t)gr * IN_DIM + k0 + u * 4);
        }
        // B: fp16, 128 rows x 8 units = 1024 cp16 (8/thread)
        #pragma unroll
        for (int i = 0; i < 8; i++) {
            int idx = i * THREADS + tid;
            int r = idx >> 3, u = idx & 7;
            cp16(sbase + SM_B + r * B_ROWB + u * 16,
                 g_Wh + (size_t)(n0 + r) * IN_DIM + k0 + u * 8);
        }
        asm volatile("cp.async.commit_group;" ::: "memory");
    };

    // ---- prologue: both stages in flight ------------------------------------
    issue(0, 0);
    issue(1, 1);

    // ---- main loop ----------------------------------------------------------
    for (int kt = 0; kt < NCHUNK; kt++) {
        const int st = kt & 1;
        asm volatile("cp.async.wait_group 1;" ::: "memory");   // chunk kt landed
        __syncthreads();

        const uint32_t sbase = sb + st * STAGE;
        #pragma unroll
        for (int s = 0; s < 4; s++) {
            // ---- A fragments: LDS.64 fp32 pairs -> cvt to fp16x2 ------------
            uint32_t af[4][4];
            #pragma unroll
            for (int mi = 0; mi < 4; mi++) {
                uint32_t base = sbase + SM_A + (a_r + mi * 16) * A32_ROWB
                              + (s * 16 + a_c) * 4;
                af[mi][0] = lds2cvt(base);                       // (r,   k..k+1)
                af[mi][1] = lds2cvt(base + 8 * A32_ROWB);        // (r+8, k..k+1)
                af[mi][2] = lds2cvt(base + 32);                  // (r,   k+8..9)
                af[mi][3] = lds2cvt(base + 8 * A32_ROWB + 32);   // (r+8, k+8..9)
            }
            // ---- B fragments: ldmatrix fp16 ---------------------------------
            const uint32_t kb = (uint32_t)(s * 16) * 2;          // 32B per k16
            uint32_t bf[8][2];
            #pragma unroll
            for (int ni = 0; ni < 8; ni++)
                ldx2(bf[ni], sbase + SM_B +
                     (warp_n * 64 + ni * 8 + brow8) * B_ROWB + kb + bcolq);

            #pragma unroll
            for (int mi = 0; mi < 4; mi++)
                #pragma unroll
                for (int ni = 0; ni < 8; ni++)
                    mma16816(acc[mi][ni], af[mi], bf[ni]);
        }

        __syncthreads();                                        // stage consumed
        if (kt + 2 < NCHUNK) issue(kt + 2, st);
        else asm volatile("cp.async.commit_group;" ::: "memory"); // keep count
    }

    // ---- epilogue: bias + relu + float2 stores ------------------------------
    #pragma unroll
    for (int mi = 0; mi < 4; mi++) {
        int r = row0 + warp_m * 64 + mi * 16 + (lane >> 2);
        #pragma unroll
        for (int ni = 0; ni < 8; ni++) {
            int col = n0 + warp_n * 64 + ni * 8 + (lane & 3) * 2;
            float2 bv = *reinterpret_cast<const float2*>(bias + col);
            if (r < M) {
                float2 o;
                o.x = fmaxf(acc[mi][ni][0] + bv.x, 0.f);
                o.y = fmaxf(acc[mi][ni][1] + bv.y, 0.f);
                *reinterpret_cast<float2*>(C + (size_t)r * OUT_DIM + col) = o;
            }
            if (r + 8 < M) {
                float2 o;
                o.x = fmaxf(acc[mi][ni][2] + bv.x, 0.f);
                o.y = fmaxf(acc[mi][ni][3] + bv.y, 0.f);
                *reinterpret_cast<float2*>(C + (size_t)(r + 8) * OUT_DIM + col) = o;
            }
        }
    }
}

// ---------------- scatter-add on column 0 -------------------------------------
__global__ void scatter_add_col0_kernel(const float* __restrict__ x,
                                        const int* __restrict__ edge_index,
                                        float* __restrict__ out,
                                        int E) {
    int e = blockIdx.x * blockDim.x + threadIdx.x;
    if (e < E) {
        int c = edge_index[E + e];            // row 1 of [2,E] int32
        atomicAdd(&out[(size_t)c * OUT_DIM], x[(size_t)e * IN_DIM]);
    }
}

// ---------------- launch ------------------------------------------------------
extern "C" void kernel_launch(void* const* d_in, const int* in_sizes, int n_in,
                              void* d_out, int out_size) {
    const float* x   = (const float*)d_in[0];
    const int*   ei  = (const int*)d_in[1];
    const float* W   = (const float*)d_in[2];
    const float* b   = (const float*)d_in[3];
    float*       out = (float*)d_out;

    const int M = in_sizes[0] / IN_DIM;
    const int E = in_sizes[1] / 2;

    cudaFuncSetAttribute(gemm_mma_kernel, cudaFuncAttributeMaxDynamicSharedMemorySize, SM_TOTAL);

    conv_W_kernel<<<(OUT_DIM * IN_DIM + 255) / 256, 256>>>(W);

    dim3 grid(OUT_DIM / BN, (M + BM - 1) / BM);   // 4 x 782
    gemm_mma_kernel<<<grid, THREADS, SM_TOTAL>>>(x, b, out, M);

    scatter_add_col0_kernel<<<(E + 255) / 256, 256>>>(x, ei, out, E);
}